// round 14
// baseline (speedup 1.0000x reference)
#include <cuda_runtime.h>
#include <cuda_fp16.h>
#include <math.h>
#include <stdint.h>

// ---------------- problem constants ----------------
#define BATCH     32
#define HDIM      64
#define WDIM      64
#define CDIM      256
#define NHEADS    8
#define WS        8
#define SS        4
#define BWIN      (BATCH*64)          // 2048
#define ROWS      (BATCH*HDIM*WDIM)   // 131072
#define HIDDEN    1024
#define CPBH      512

// fp16 GEMM tiling: CTA 128x128, BK=32 halves (64B rows), 128 threads, warp 64x64
#define ROWB     80                    // bytes per smem row (64 data + 16 pad)
#define SEC_B    10240                 // B section offset (128*80)
#define STAGE_B  20480
#define SMEM_GEMM (2*STAGE_B)          // 40960 -> 5 CTAs/SM

// ---------------- scratch (device globals, no alloc) ----------------
__device__ float  g_qkv[3u*2048u*8u*64u*32u];          // fp32 (attention precision)
__device__ __align__(128) __half g_attn_h[(size_t)131072*256];
__device__ float  g_proj[(size_t)131072*256];
__device__ float  g_x1[(size_t)131072*256];
__device__ __align__(128) __half g_x1h[(size_t)131072*256];
__device__ __align__(128) __half g_hidh[(size_t)131072*1024];
__device__ float  g_h2[(size_t)131072*256];
__device__ __align__(128) __half g_xh[(size_t)131072*256];
__device__ float  g_bias_table[225*8];
__device__ float  g_rpb[8*64*64];
__device__ int    g_gather[131072];
__device__ __align__(128) __half g_wq[768*256];
__device__ __align__(128) __half g_wp[256*256];
__device__ __align__(128) __half g_w1[1024*256];
__device__ __align__(128) __half g_w2[256*1024];

// ---------------- helpers ----------------
__device__ __forceinline__ uint32_t smem_u32(const void* p){
    uint32_t a;
    asm("{ .reg .u64 t; cvta.to.shared.u64 t, %1; cvt.u32.u64 %0, t; }" : "=r"(a) : "l"(p));
    return a;
}
#define CP16(dst, src) asm volatile("cp.async.cg.shared.global [%0], [%1], 16;" :: "r"(dst), "l"(src))
#define CP_COMMIT()    asm volatile("cp.async.commit_group;" ::: "memory")
#define CP_WAIT1()     asm volatile("cp.async.wait_group 1;" ::: "memory")

__device__ __forceinline__ void mma_f16(float* c, const uint32_t* a, const uint32_t* b){
    asm volatile("mma.sync.aligned.m16n8k16.row.col.f32.f16.f16.f32 "
      "{%0,%1,%2,%3}, {%4,%5,%6,%7}, {%8,%9}, {%0,%1,%2,%3};\n"
      : "+f"(c[0]), "+f"(c[1]), "+f"(c[2]), "+f"(c[3])
      : "r"(a[0]), "r"(a[1]), "r"(a[2]), "r"(a[3]), "r"(b[0]), "r"(b[1]));
}
__device__ __forceinline__ float gelu_t(float x){
    float x3 = x*x*x;
    float t  = tanhf(0.7978845608028654f * (x + 0.044715f*x3));
    return 0.5f * x * (1.0f + t);
}
__device__ __forceinline__ float warp_sum(float v){
#pragma unroll
    for (int o = 16; o > 0; o >>= 1) v += __shfl_xor_sync(0xffffffffu, v, o);
    return v;
}

// ---------------- fused setup: gather index + x -> fp16 ----------------
__global__ void k_setup(const float* __restrict__ x){
    int gid = blockIdx.x * 256 + threadIdx.x;
    size_t i = (size_t)gid * 4;
    float4 v = *(const float4*)(x + i);
    __half2* oh = (__half2*)(g_xh + i);
    oh[0] = __floats2half2_rn(v.x, v.y);
    oh[1] = __floats2half2_rn(v.z, v.w);
    if (gid < ROWS){
        int b_  = gid >> 6;
        int n   = gid & 63;
        int b   = b_ >> 6;
        int wid = b_ & 63;
        int h = ((wid >> 3)*8 + (n >> 3) + SS) & 63;
        int w = ((wid & 7)*8 + (n & 7) + SS) & 63;
        g_gather[gid] = b*(HDIM*WDIM) + h*WDIM + w;
    }
}

// ---------------- fused CPB MLP + rpb table (single block) ----------------
__device__ __forceinline__ float cpb_coord(int c){
    float t = (float)c * (8.0f/7.0f);
    float v = log2f(fabsf(t) + 1.0f) * (1.0f/3.0f);
    return t < 0.f ? -v : v;
}
__global__ void k_cpb_rpb(const float* __restrict__ w1, const float* __restrict__ b1,
                          const float* __restrict__ w2){
    int p = threadIdx.x;
    if (p < 225){
        float t0 = cpb_coord(p/15 - 7);
        float t1 = cpb_coord(p%15 - 7);
        float out[8];
#pragma unroll
        for (int h = 0; h < 8; h++) out[h] = 0.f;
        for (int j = 0; j < CPBH; j++){
            float hdn = fmaxf(t0*w1[j] + t1*w1[CPBH + j] + b1[j], 0.f);
#pragma unroll
            for (int h = 0; h < 8; h++) out[h] = fmaf(hdn, w2[j*8 + h], out[h]);
        }
#pragma unroll
        for (int h = 0; h < 8; h++) g_bias_table[p*8 + h] = out[h];
    }
    __syncthreads();
    for (int idx = threadIdx.x; idx < 8*64*64; idx += 256){
        int h = idx >> 12;
        int n = (idx >> 6) & 63;
        int m = idx & 63;
        int dh = (n>>3) - (m>>3) + 7;
        int dw = (n&7)  - (m&7)  + 7;
        float b = g_bias_table[(dh*15 + dw)*8 + h];
        g_rpb[idx] = 16.0f / (1.0f + expf(-b));
    }
}

// ---------------- fused weight transposes: W[K,N] -> half Wt[N,K] ----------------
__global__ void k_transpose_all(const float* __restrict__ w_qkv,
                                const float* __restrict__ w_proj,
                                const float* __restrict__ w_fc1,
                                const float* __restrict__ w_fc2){
    const float* W; __half* Wt; int K, N;
    switch (blockIdx.z){
        case 0: W = w_qkv;  Wt = g_wq; K = 256;  N = 768;  break;
        case 1: W = w_proj; Wt = g_wp; K = 256;  N = 256;  break;
        case 2: W = w_fc1;  Wt = g_w1; K = 256;  N = 1024; break;
        default:W = w_fc2;  Wt = g_w2; K = 1024; N = 256;  break;
    }
    int n0 = blockIdx.x*32, k0 = blockIdx.y*32;
    if (n0 >= N || k0 >= K) return;
    __shared__ float t[32][33];
    for (int r = threadIdx.y; r < 32; r += 8)
        t[r][threadIdx.x] = W[(size_t)(k0+r)*N + n0 + threadIdx.x];
    __syncthreads();
    for (int r = threadIdx.y; r < 32; r += 8)
        Wt[(size_t)(n0+r)*K + k0 + threadIdx.x] = __float2half_rn(t[threadIdx.x][r]);
}

// ============================================================================
// fp16 GEMM core: m16n8k16, BK=32, 2-stage cp.async ring, 5 CTAs/SM.
// smem rows: 64 data bytes (32 halves) + 16B pad -> fragment loads conflict-free
// (bank = (20*lr + lc) mod 32, all 32 distinct).
// ============================================================================

__device__ __forceinline__ void compute_tile_h(const char* sA, const char* sB,
        int wm, int wn, int lr, int lc, float acc[4][8][4]){
#pragma unroll
    for (int ks = 0; ks < 2; ks++){
        const int kb = ks*32 + lc*4;
        uint32_t a[4][4], b[8][2];
#pragma unroll
        for (int mt = 0; mt < 4; mt++){
            int r = wm + mt*16 + lr;
            a[mt][0] = *(const uint32_t*)(sA + r*ROWB + kb);
            a[mt][1] = *(const uint32_t*)(sA + (r+8)*ROWB + kb);
            a[mt][2] = *(const uint32_t*)(sA + r*ROWB + kb + 16);
            a[mt][3] = *(const uint32_t*)(sA + (r+8)*ROWB + kb + 16);
        }
#pragma unroll
        for (int nt = 0; nt < 8; nt++){
            int c = wn + nt*8 + lr;
            b[nt][0] = *(const uint32_t*)(sB + c*ROWB + kb);
            b[nt][1] = *(const uint32_t*)(sB + c*ROWB + kb + 16);
        }
#pragma unroll
        for (int mt = 0; mt < 4; mt++)
#pragma unroll
            for (int nt = 0; nt < 8; nt++)
                mma_f16(acc[mt][nt], a[mt], b[nt]);
    }
}

// thread t stages row t of A and row t of B: 4 x 16B each (64B = BK halves)
__device__ __forceinline__ void issue_stage_h(uint32_t da, uint32_t db,
        const char* arow, const char* brow, int i){
#pragma unroll
    for (int c = 0; c < 4; c++){
        CP16(da + c*16, arow + i*64 + c*16);
        CP16(db + c*16, brow + i*64 + c*16);
    }
}

template<int ACT, int HOUT>
__global__ __launch_bounds__(128) void gemm_h(const __half* __restrict__ A,
        const __half* __restrict__ Bt, const float* __restrict__ bias,
        void* __restrict__ Cv, int K, int Nn){
    extern __shared__ char smc[];
    uint32_t sbase = smem_u32(smc);
    const int tid = threadIdx.x;
    const int wid = tid >> 5, lane = tid & 31;
    const int wm = (wid >> 1)*64, wn = (wid & 1)*64;
    const int lr = lane >> 2, lc = lane & 3;
    const int bm = blockIdx.y * 128;
    const int bn = blockIdx.x * 128;

    const char* arow = (const char*)(A  + (size_t)(bm + tid)*K);
    const char* brow = (const char*)(Bt + (size_t)(bn + tid)*K);
    const uint32_t da = sbase + tid*ROWB;
    const uint32_t db = sbase + SEC_B + tid*ROWB;

    float acc[4][8][4];
#pragma unroll
    for (int mt = 0; mt < 4; mt++)
#pragma unroll
        for (int nt = 0; nt < 8; nt++)
#pragma unroll
            for (int q = 0; q < 4; q++) acc[mt][nt][q] = 0.f;

    const int S = K / 32;
    issue_stage_h(da, db, arow, brow, 0); CP_COMMIT();
    issue_stage_h(da + STAGE_B, db + STAGE_B, arow, brow, 1); CP_COMMIT();

    for (int i = 0; i < S; i++){
        CP_WAIT1();
        __syncthreads();
        const char* st = smc + (i & 1)*STAGE_B;
        compute_tile_h(st, st + SEC_B, wm, wn, lr, lc, acc);
        __syncthreads();
        if (i + 2 < S)
            issue_stage_h(da + (i & 1)*STAGE_B, db + (i & 1)*STAGE_B, arow, brow, i+2);
        CP_COMMIT();
    }

#pragma unroll
    for (int mt = 0; mt < 4; mt++){
        int r0 = bm + wm + mt*16 + lr;
#pragma unroll
        for (int nt = 0; nt < 8; nt++){
            int c0 = bn + wn + nt*8 + lc*2;
            float b0 = bias[c0], b1 = bias[c0+1];
            float v0 = acc[mt][nt][0] + b0, v1 = acc[mt][nt][1] + b1;
            float v2 = acc[mt][nt][2] + b0, v3 = acc[mt][nt][3] + b1;
            if (ACT == 1){ v0=gelu_t(v0); v1=gelu_t(v1); v2=gelu_t(v2); v3=gelu_t(v3); }
            if (HOUT){
                __half* C = (__half*)Cv;
                *(__half2*)(C + (size_t)r0*Nn + c0)     = __floats2half2_rn(v0, v1);
                *(__half2*)(C + (size_t)(r0+8)*Nn + c0) = __floats2half2_rn(v2, v3);
            } else {
                float* C = (float*)Cv;
                *(float2*)(C + (size_t)r0*Nn + c0)     = make_float2(v0, v1);
                *(float2*)(C + (size_t)(r0+8)*Nn + c0) = make_float2(v2, v3);
            }
        }
    }
}

// QKV: A rows gathered from g_xh, fp32 scatter epilogue into g_qkv
__global__ __launch_bounds__(128) void gemm_h_qkv(const __half* __restrict__ Xh,
        const __half* __restrict__ Bt, const float* __restrict__ qb,
        const float* __restrict__ vb){
    extern __shared__ char smc[];
    uint32_t sbase = smem_u32(smc);
    const int tid = threadIdx.x;
    const int wid = tid >> 5, lane = tid & 31;
    const int wm = (wid >> 1)*64, wn = (wid & 1)*64;
    const int lr = lane >> 2, lc = lane & 3;
    const int bm = blockIdx.y * 128;
    const int bn = blockIdx.x * 128;
    const int K = 256;

    const char* arow = (const char*)(Xh + (size_t)g_gather[bm + tid]*K);
    const char* brow = (const char*)(Bt + (size_t)(bn + tid)*K);
    const uint32_t da = sbase + tid*ROWB;
    const uint32_t db = sbase + SEC_B + tid*ROWB;

    float acc[4][8][4];
#pragma unroll
    for (int mt = 0; mt < 4; mt++)
#pragma unroll
        for (int nt = 0; nt < 8; nt++)
#pragma unroll
            for (int q = 0; q < 4; q++) acc[mt][nt][q] = 0.f;

    const int S = K / 32;   // 8
    issue_stage_h(da, db, arow, brow, 0); CP_COMMIT();
    issue_stage_h(da + STAGE_B, db + STAGE_B, arow, brow, 1); CP_COMMIT();

    for (int i = 0; i < S; i++){
        CP_WAIT1();
        __syncthreads();
        const char* st = smc + (i & 1)*STAGE_B;
        compute_tile_h(st, st + SEC_B, wm, wn, lr, lc, acc);
        __syncthreads();
        if (i + 2 < S)
            issue_stage_h(da + (i & 1)*STAGE_B, db + (i & 1)*STAGE_B, arow, brow, i+2);
        CP_COMMIT();
    }

#pragma unroll
    for (int mt = 0; mt < 4; mt++){
        int r0 = bm + wm + mt*16 + lr;
        int b0_ = r0 >> 6, n0 = r0 & 63;
        int b1_ = (r0+8) >> 6, n1 = (r0+8) & 63;
#pragma unroll
        for (int nt = 0; nt < 8; nt++){
            int c0 = bn + wn + nt*8 + lc*2;
            int s2 = c0 >> 8, rem = c0 & 255;
            int h = rem >> 5, d = rem & 31;
            float bv0, bv1;
            if (s2 == 0){ bv0 = qb[rem]; bv1 = qb[rem+1]; }
            else if (s2 == 2){ bv0 = vb[rem]; bv1 = vb[rem+1]; }
            else { bv0 = 0.f; bv1 = 0.f; }
            size_t hb = ((size_t)(s2*BWIN)*NHEADS + (size_t)h)*2048 + d;
            *(float2*)(g_qkv + hb + ((size_t)b0_*NHEADS)*2048 + n0*32) =
                make_float2(acc[mt][nt][0] + bv0, acc[mt][nt][1] + bv1);
            *(float2*)(g_qkv + hb + ((size_t)b1_*NHEADS)*2048 + n1*32) =
                make_float2(acc[mt][nt][2] + bv0, acc[mt][nt][3] + bv1);
        }
    }
}

// ---------------- attention: one (window, head) per block, chunked online softmax ----------------
__global__ __launch_bounds__(64) void k_attn(const float* __restrict__ ls){
    const int b_ = blockIdx.x;
    const int hh = blockIdx.y;
    const int n  = threadIdx.x;
    __shared__ float kn[64][32];
    __shared__ float vs[64][32];
    __shared__ int   rg[64];

    const size_t sstride = (size_t)BWIN * NHEADS * 64 * 32;
    const size_t base = ((size_t)b_*NHEADS + hh)*(64*32) + n*32;
    const float* qp = g_qkv + base;
    const float* kp = g_qkv + sstride + base;
    const float* vp = g_qkv + 2*sstride + base;

    float qr[32]; float sacc = 0.f;
#pragma unroll
    for (int d = 0; d < 32; d++){ qr[d] = qp[d]; sacc = fmaf(qr[d], qr[d], sacc); }
    float qi = rsqrtf(fmaxf(sacc, 1e-12f));
#pragma unroll
    for (int d = 0; d < 32; d++) qr[d] *= qi;

    sacc = 0.f; float kr[32];
#pragma unroll
    for (int d = 0; d < 32; d++){ kr[d] = kp[d]; sacc = fmaf(kr[d], kr[d], sacc); }
    float ki = rsqrtf(fmaxf(sacc, 1e-12f));
#pragma unroll
    for (int d = 0; d < 32; d++) kn[n][d] = kr[d]*ki;
#pragma unroll
    for (int d = 0; d < 32; d++) vs[n][d] = vp[d];

    int wid = b_ & 63;
    int gh = (wid >> 3)*8 + (n >> 3);
    int gw = (wid & 7)*8 + (n & 7);
    int hr = gh < 56 ? 0 : (gh < 60 ? 1 : 2);
    int wr = gw < 56 ? 0 : (gw < 60 ? 1 : 2);
    rg[n] = hr*3 + wr;
    __syncthreads();

    float scale = expf(fminf(ls[hh], 4.6051701859880914f));
    const float* rp = g_rpb + (hh*64 + n)*64;
    int myreg = hr*3 + wr;

    float mx = -1e30f, sum = 0.f;
    float acc[32];
#pragma unroll
    for (int d = 0; d < 32; d++) acc[d] = 0.f;

    for (int cb = 0; cb < 64; cb += 16){
        float lg[16]; float cmax = -1e30f;
#pragma unroll
        for (int j = 0; j < 16; j++){
            int m = cb + j;
            float dot = 0.f;
#pragma unroll
            for (int d = 0; d < 32; d++) dot = fmaf(qr[d], kn[m][d], dot);
            float v = fmaf(dot, scale, rp[m]);
            if (rg[m] != myreg) v -= 100.f;
            lg[j] = v;
            cmax = fmaxf(cmax, v);
        }
        float nm = fmaxf(mx, cmax);
        float corr = expf(mx - nm);
        sum *= corr;
#pragma unroll
        for (int d = 0; d < 32; d++) acc[d] *= corr;
#pragma unroll
        for (int j = 0; j < 16; j++){
            float p = expf(lg[j] - nm);
            sum += p;
            const float* vr = vs[cb + j];
#pragma unroll
            for (int d = 0; d < 32; d++) acc[d] = fmaf(p, vr[d], acc[d]);
        }
        mx = nm;
    }
    float inv = 1.f / sum;

    __half* op = g_attn_h + ((size_t)b_*64 + n)*CDIM + hh*32;
#pragma unroll
    for (int d = 0; d < 32; d += 2)
        *(__half2*)(op + d) = __floats2half2_rn(acc[d]*inv, acc[d+1]*inv);
}

// ---------------- LN1 + residual, scatter; fp32 residual + fp16 GEMM operand ----------------
__global__ void k_ln1(const float* __restrict__ x, const float* __restrict__ sc,
                      const float* __restrict__ bi){
    int r    = blockIdx.x*8 + (threadIdx.x >> 5);
    int lane = threadIdx.x & 31;
    const float* row = g_proj + (size_t)r*CDIM;
    float v[8]; float s = 0.f;
#pragma unroll
    for (int t = 0; t < 8; t++){ v[t] = row[lane + t*32]; s += v[t]; }
    s = warp_sum(s);
    float mu = s * (1.f/256.f);
    float var = 0.f;
#pragma unroll
    for (int t = 0; t < 8; t++){ float d = v[t]-mu; var = fmaf(d, d, var); }
    var = warp_sum(var) * (1.f/256.f);
    float invs = rsqrtf(var + 1e-6f);
    int dst = g_gather[r];
    const float* xr = x + (size_t)dst*CDIM;
    float*  o  = g_x1  + (size_t)dst*CDIM;
    __half* oh = g_x1h + (size_t)dst*CDIM;
#pragma unroll
    for (int t = 0; t < 8; t++){
        int c = lane + t*32;
        float val = xr[c] + (v[t]-mu)*invs*sc[c] + bi[c];
        o[c]  = val;
        oh[c] = __float2half_rn(val);
    }
}

// ---------------- LN2 + residual -> d_out ----------------
__global__ void k_ln2(const float* __restrict__ sc, const float* __restrict__ bi,
                      float* __restrict__ out){
    int r    = blockIdx.x*8 + (threadIdx.x >> 5);
    int lane = threadIdx.x & 31;
    const float* row = g_h2 + (size_t)r*CDIM;
    float v[8]; float s = 0.f;
#pragma unroll
    for (int t = 0; t < 8; t++){ v[t] = row[lane + t*32]; s += v[t]; }
    s = warp_sum(s);
    float mu = s * (1.f/256.f);
    float var = 0.f;
#pragma unroll
    for (int t = 0; t < 8; t++){ float d = v[t]-mu; var = fmaf(d, d, var); }
    var = warp_sum(var) * (1.f/256.f);
    float invs = rsqrtf(var + 1e-6f);
    const float* x1r = g_x1 + (size_t)r*CDIM;
    float* o = out + (size_t)r*CDIM;
#pragma unroll
    for (int t = 0; t < 8; t++){
        int c = lane + t*32;
        o[c] = x1r[c] + (v[t]-mu)*invs*sc[c] + bi[c];
    }
}

// ---------------- launch ----------------
extern "C" void kernel_launch(void* const* d_in, const int* in_sizes, int n_in,
                              void* d_out, int out_size){
    const float* x      = (const float*)d_in[0];
    const float* qkv_w  = (const float*)d_in[1];
    const float* q_bias = (const float*)d_in[2];
    const float* v_bias = (const float*)d_in[3];
    const float* lscale = (const float*)d_in[4];
    const float* cpb_w1 = (const float*)d_in[5];
    const float* cpb_b1 = (const float*)d_in[6];
    const float* cpb_w2 = (const float*)d_in[7];
    const float* proj_w = (const float*)d_in[8];
    const float* proj_b = (const float*)d_in[9];
    const float* n1s    = (const float*)d_in[10];
    const float* n1b    = (const float*)d_in[11];
    const float* n2s    = (const float*)d_in[12];
    const float* n2b    = (const float*)d_in[13];
    const float* fc1_w  = (const float*)d_in[14];
    const float* fc1_b  = (const float*)d_in[15];
    const float* fc2_w  = (const float*)d_in[16];
    const float* fc2_b  = (const float*)d_in[17];
    float* out = (float*)d_out;

    void *p_xh, *p_attn_h, *p_proj, *p_x1h, *p_hidh, *p_h2;
    void *p_wq, *p_wp, *p_w1, *p_w2;
    cudaGetSymbolAddress(&p_xh,     g_xh);
    cudaGetSymbolAddress(&p_attn_h, g_attn_h);
    cudaGetSymbolAddress(&p_proj,   g_proj);
    cudaGetSymbolAddress(&p_x1h,    g_x1h);
    cudaGetSymbolAddress(&p_hidh,   g_hidh);
    cudaGetSymbolAddress(&p_h2,     g_h2);
    cudaGetSymbolAddress(&p_wq,     g_wq);
    cudaGetSymbolAddress(&p_wp,     g_wp);
    cudaGetSymbolAddress(&p_w1,     g_w1);
    cudaGetSymbolAddress(&p_w2,     g_w2);

    cudaFuncSetAttribute(gemm_h<0,0>, cudaFuncAttributeMaxDynamicSharedMemorySize, SMEM_GEMM);
    cudaFuncSetAttribute(gemm_h<1,1>, cudaFuncAttributeMaxDynamicSharedMemorySize, SMEM_GEMM);
    cudaFuncSetAttribute(gemm_h_qkv,  cudaFuncAttributeMaxDynamicSharedMemorySize, SMEM_GEMM);

    // 0: gather + x->fp16
    k_setup<<<(ROWS*CDIM/4)/256, 256>>>(x);
    // 1: CPB MLP + rpb
    k_cpb_rpb<<<1, 256>>>(cpb_w1, cpb_b1, cpb_w2);
    // 2: all weight transposes (fp16)
    k_transpose_all<<<dim3(32, 32, 4), dim3(32, 8)>>>(qkv_w, proj_w, fc1_w, fc2_w);
    // 3: QKV (131072 x 256) @ (256 x 768)
    gemm_h_qkv<<<dim3(6, ROWS/128), 128, SMEM_GEMM>>>((const __half*)p_xh,
            (const __half*)p_wq, q_bias, v_bias);
    // 4: attention
    k_attn<<<dim3(BWIN, NHEADS), 64>>>(lscale);
    // 5: proj (131072 x 256) @ (256 x 256)   <- ncu -s 5 lands here
    gemm_h<0,0><<<dim3(2, ROWS/128), 128, SMEM_GEMM>>>((const __half*)p_attn_h,
            (const __half*)p_wp, proj_b, p_proj, 256, 256);
    // 6: LN1 + residual + scatter
    k_ln1<<<ROWS/8, 256>>>(x, n1s, n1b);
    // 7: FC1 + GELU -> fp16
    gemm_h<1,1><<<dim3(8, ROWS/128), 128, SMEM_GEMM>>>((const __half*)p_x1h,
            (const __half*)p_w1, fc1_b, p_hidh, 256, 1024);
    // 8: FC2
    gemm_h<0,0><<<dim3(2, ROWS/128), 128, SMEM_GEMM>>>((const __half*)p_hidh,
            (const __half*)p_w2, fc2_b, p_h2, 1024, 256);
    // 9: LN2 + residual -> out
    k_ln2<<<ROWS/8, 256>>>(n2s, n2b, out);
}

// round 15
// speedup vs baseline: 1.1165x; 1.1165x over previous
#include <cuda_runtime.h>
#include <cuda_fp16.h>
#include <math.h>
#include <stdint.h>

// ---------------- problem constants ----------------
#define BATCH     32
#define HDIM      64
#define WDIM      64
#define CDIM      256
#define NHEADS    8
#define WS        8
#define SS        4
#define BWIN      (BATCH*64)          // 2048
#define ROWS      (BATCH*HDIM*WDIM)   // 131072
#define HIDDEN    1024
#define CPBH      512

// fp16 GEMM tiling: CTA 128x128, BK=32 halves (64B rows), 256 threads (8 warps 2x4),
// warp tile 64x32, 4-stage cp.async ring.
#define ROWB     80                    // bytes per smem row (64 data + 16 pad)
#define SEC_B    10240                 // B section offset (128*80)
#define STAGE_B  20480
#define NSTAGE   4
#define SMEM_GEMM (NSTAGE*STAGE_B)     // 81920 -> 2 CTAs/SM (smem+regs)

// ---------------- scratch (device globals, no alloc) ----------------
__device__ float  g_qkv[3u*2048u*8u*64u*32u];          // fp32 (attention precision)
__device__ __align__(128) __half g_attn_h[(size_t)131072*256];
__device__ float  g_proj[(size_t)131072*256];
__device__ float  g_x1[(size_t)131072*256];
__device__ __align__(128) __half g_x1h[(size_t)131072*256];
__device__ __align__(128) __half g_hidh[(size_t)131072*1024];
__device__ float  g_h2[(size_t)131072*256];
__device__ __align__(128) __half g_xh[(size_t)131072*256];
__device__ float  g_bias_table[225*8];
__device__ float  g_rpb[8*64*64];
__device__ int    g_gather[131072];
__device__ __align__(128) __half g_wq[768*256];
__device__ __align__(128) __half g_wp[256*256];
__device__ __align__(128) __half g_w1[1024*256];
__device__ __align__(128) __half g_w2[256*1024];

// ---------------- helpers ----------------
__device__ __forceinline__ uint32_t smem_u32(const void* p){
    uint32_t a;
    asm("{ .reg .u64 t; cvta.to.shared.u64 t, %1; cvt.u32.u64 %0, t; }" : "=r"(a) : "l"(p));
    return a;
}
#define CP16(dst, src) asm volatile("cp.async.cg.shared.global [%0], [%1], 16;" :: "r"(dst), "l"(src))
#define CP_COMMIT()    asm volatile("cp.async.commit_group;" ::: "memory")
#define CP_WAIT2()     asm volatile("cp.async.wait_group 2;" ::: "memory")

__device__ __forceinline__ void mma_f16(float* c, const uint32_t* a, const uint32_t* b){
    asm volatile("mma.sync.aligned.m16n8k16.row.col.f32.f16.f16.f32 "
      "{%0,%1,%2,%3}, {%4,%5,%6,%7}, {%8,%9}, {%0,%1,%2,%3};\n"
      : "+f"(c[0]), "+f"(c[1]), "+f"(c[2]), "+f"(c[3])
      : "r"(a[0]), "r"(a[1]), "r"(a[2]), "r"(a[3]), "r"(b[0]), "r"(b[1]));
}
__device__ __forceinline__ float gelu_t(float x){
    float x3 = x*x*x;
    float t  = tanhf(0.7978845608028654f * (x + 0.044715f*x3));
    return 0.5f * x * (1.0f + t);
}
__device__ __forceinline__ float warp_sum(float v){
#pragma unroll
    for (int o = 16; o > 0; o >>= 1) v += __shfl_xor_sync(0xffffffffu, v, o);
    return v;
}

// ---------------- fused setup: gather index + x -> fp16 ----------------
__global__ void k_setup(const float* __restrict__ x){
    int gid = blockIdx.x * 256 + threadIdx.x;
    size_t i = (size_t)gid * 4;
    float4 v = *(const float4*)(x + i);
    __half2* oh = (__half2*)(g_xh + i);
    oh[0] = __floats2half2_rn(v.x, v.y);
    oh[1] = __floats2half2_rn(v.z, v.w);
    if (gid < ROWS){
        int b_  = gid >> 6;
        int n   = gid & 63;
        int b   = b_ >> 6;
        int wid = b_ & 63;
        int h = ((wid >> 3)*8 + (n >> 3) + SS) & 63;
        int w = ((wid & 7)*8 + (n & 7) + SS) & 63;
        g_gather[gid] = b*(HDIM*WDIM) + h*WDIM + w;
    }
}

// ---------------- fused CPB MLP + rpb table (single block) ----------------
__device__ __forceinline__ float cpb_coord(int c){
    float t = (float)c * (8.0f/7.0f);
    float v = log2f(fabsf(t) + 1.0f) * (1.0f/3.0f);
    return t < 0.f ? -v : v;
}
__global__ void k_cpb_rpb(const float* __restrict__ w1, const float* __restrict__ b1,
                          const float* __restrict__ w2){
    int p = threadIdx.x;
    if (p < 225){
        float t0 = cpb_coord(p/15 - 7);
        float t1 = cpb_coord(p%15 - 7);
        float out[8];
#pragma unroll
        for (int h = 0; h < 8; h++) out[h] = 0.f;
        for (int j = 0; j < CPBH; j++){
            float hdn = fmaxf(t0*w1[j] + t1*w1[CPBH + j] + b1[j], 0.f);
#pragma unroll
            for (int h = 0; h < 8; h++) out[h] = fmaf(hdn, w2[j*8 + h], out[h]);
        }
#pragma unroll
        for (int h = 0; h < 8; h++) g_bias_table[p*8 + h] = out[h];
    }
    __syncthreads();
    for (int idx = threadIdx.x; idx < 8*64*64; idx += 256){
        int h = idx >> 12;
        int n = (idx >> 6) & 63;
        int m = idx & 63;
        int dh = (n>>3) - (m>>3) + 7;
        int dw = (n&7)  - (m&7)  + 7;
        float b = g_bias_table[(dh*15 + dw)*8 + h];
        g_rpb[idx] = 16.0f / (1.0f + expf(-b));
    }
}

// ---------------- fused weight transposes: W[K,N] -> half Wt[N,K] ----------------
__global__ void k_transpose_all(const float* __restrict__ w_qkv,
                                const float* __restrict__ w_proj,
                                const float* __restrict__ w_fc1,
                                const float* __restrict__ w_fc2){
    const float* W; __half* Wt; int K, N;
    switch (blockIdx.z){
        case 0: W = w_qkv;  Wt = g_wq; K = 256;  N = 768;  break;
        case 1: W = w_proj; Wt = g_wp; K = 256;  N = 256;  break;
        case 2: W = w_fc1;  Wt = g_w1; K = 256;  N = 1024; break;
        default:W = w_fc2;  Wt = g_w2; K = 1024; N = 256;  break;
    }
    int n0 = blockIdx.x*32, k0 = blockIdx.y*32;
    if (n0 >= N || k0 >= K) return;
    __shared__ float t[32][33];
    for (int r = threadIdx.y; r < 32; r += 8)
        t[r][threadIdx.x] = W[(size_t)(k0+r)*N + n0 + threadIdx.x];
    __syncthreads();
    for (int r = threadIdx.y; r < 32; r += 8)
        Wt[(size_t)(n0+r)*K + k0 + threadIdx.x] = __float2half_rn(t[threadIdx.x][r]);
}

// ============================================================================
// fp16 GEMM core: m16n8k16, BK=32, 4-stage cp.async ring, 256 thr, warp 64x32.
// Staging: thread t stages 32B of A row (t>>1) and 32B of B row (t>>1),
// halves selected by t&1. Fragment loads conflict-free (bank = 20*lr+lc mod 32).
// ============================================================================

__device__ __forceinline__ void compute_tile_h(const char* sA, const char* sB,
        int wm, int wn, int lr, int lc, float acc[4][4][4]){
#pragma unroll
    for (int ks = 0; ks < 2; ks++){
        const int kb = ks*32 + lc*4;
        uint32_t a[4][4], b[4][2];
#pragma unroll
        for (int mt = 0; mt < 4; mt++){
            int r = wm + mt*16 + lr;
            a[mt][0] = *(const uint32_t*)(sA + r*ROWB + kb);
            a[mt][1] = *(const uint32_t*)(sA + (r+8)*ROWB + kb);
            a[mt][2] = *(const uint32_t*)(sA + r*ROWB + kb + 16);
            a[mt][3] = *(const uint32_t*)(sA + (r+8)*ROWB + kb + 16);
        }
#pragma unroll
        for (int nt = 0; nt < 4; nt++){
            int c = wn + nt*8 + lr;
            b[nt][0] = *(const uint32_t*)(sB + c*ROWB + kb);
            b[nt][1] = *(const uint32_t*)(sB + c*ROWB + kb + 16);
        }
#pragma unroll
        for (int mt = 0; mt < 4; mt++)
#pragma unroll
            for (int nt = 0; nt < 4; nt++)
                mma_f16(acc[mt][nt], a[mt], b[nt]);
    }
}

// thread stages 32B of one A row and 32B of one B row per stage
__device__ __forceinline__ void issue_stage_h(uint32_t da, uint32_t db,
        const char* ap, const char* bp, int i){
    CP16(da,      ap + i*64);
    CP16(da + 16, ap + i*64 + 16);
    CP16(db,      bp + i*64);
    CP16(db + 16, bp + i*64 + 16);
}

template<int ACT, int HOUT>
__global__ __launch_bounds__(256, 2) void gemm_h(const __half* __restrict__ A,
        const __half* __restrict__ Bt, const float* __restrict__ bias,
        void* __restrict__ Cv, int K, int Nn){
    extern __shared__ char smc[];
    uint32_t sbase = smem_u32(smc);
    const int tid = threadIdx.x;
    const int wid = tid >> 5, lane = tid & 31;
    const int wm = (wid >> 2)*64, wn = (wid & 3)*32;
    const int lr = lane >> 2, lc = lane & 3;
    const int bm = blockIdx.y * 128;
    const int bn = blockIdx.x * 128;

    const int srow = tid >> 1, soff = (tid & 1)*32;
    const char* ap = (const char*)(A  + (size_t)(bm + srow)*K) + soff;
    const char* bp = (const char*)(Bt + (size_t)(bn + srow)*K) + soff;
    const uint32_t da = sbase + srow*ROWB + soff;
    const uint32_t db = sbase + SEC_B + srow*ROWB + soff;

    float acc[4][4][4];
#pragma unroll
    for (int mt = 0; mt < 4; mt++)
#pragma unroll
        for (int nt = 0; nt < 4; nt++)
#pragma unroll
            for (int q = 0; q < 4; q++) acc[mt][nt][q] = 0.f;

    const int S = K / 32;
#pragma unroll
    for (int p = 0; p < 3; p++){
        issue_stage_h(da + p*STAGE_B, db + p*STAGE_B, ap, bp, p);
        CP_COMMIT();
    }

    for (int i = 0; i < S; i++){
        CP_WAIT2();
        __syncthreads();
        const char* st = smc + (i & 3)*STAGE_B;
        compute_tile_h(st, st + SEC_B, wm, wn, lr, lc, acc);
        __syncthreads();
        if (i + 3 < S){
            int s = (i + 3) & 3;
            issue_stage_h(da + s*STAGE_B, db + s*STAGE_B, ap, bp, i + 3);
        }
        CP_COMMIT();
    }

#pragma unroll
    for (int mt = 0; mt < 4; mt++){
        int r0 = bm + wm + mt*16 + lr;
#pragma unroll
        for (int nt = 0; nt < 4; nt++){
            int c0 = bn + wn + nt*8 + lc*2;
            float b0 = bias[c0], b1 = bias[c0+1];
            float v0 = acc[mt][nt][0] + b0, v1 = acc[mt][nt][1] + b1;
            float v2 = acc[mt][nt][2] + b0, v3 = acc[mt][nt][3] + b1;
            if (ACT == 1){ v0=gelu_t(v0); v1=gelu_t(v1); v2=gelu_t(v2); v3=gelu_t(v3); }
            if (HOUT){
                __half* C = (__half*)Cv;
                *(__half2*)(C + (size_t)r0*Nn + c0)     = __floats2half2_rn(v0, v1);
                *(__half2*)(C + (size_t)(r0+8)*Nn + c0) = __floats2half2_rn(v2, v3);
            } else {
                float* C = (float*)Cv;
                *(float2*)(C + (size_t)r0*Nn + c0)     = make_float2(v0, v1);
                *(float2*)(C + (size_t)(r0+8)*Nn + c0) = make_float2(v2, v3);
            }
        }
    }
}

// QKV: A rows gathered from g_xh, fp32 scatter epilogue into g_qkv
__global__ __launch_bounds__(256, 2) void gemm_h_qkv(const __half* __restrict__ Xh,
        const __half* __restrict__ Bt, const float* __restrict__ qb,
        const float* __restrict__ vb){
    extern __shared__ char smc[];
    uint32_t sbase = smem_u32(smc);
    const int tid = threadIdx.x;
    const int wid = tid >> 5, lane = tid & 31;
    const int wm = (wid >> 2)*64, wn = (wid & 3)*32;
    const int lr = lane >> 2, lc = lane & 3;
    const int bm = blockIdx.y * 128;
    const int bn = blockIdx.x * 128;
    const int K = 256;

    const int srow = tid >> 1, soff = (tid & 1)*32;
    const char* ap = (const char*)(Xh + (size_t)g_gather[bm + srow]*K) + soff;
    const char* bp = (const char*)(Bt + (size_t)(bn + srow)*K) + soff;
    const uint32_t da = sbase + srow*ROWB + soff;
    const uint32_t db = sbase + SEC_B + srow*ROWB + soff;

    float acc[4][4][4];
#pragma unroll
    for (int mt = 0; mt < 4; mt++)
#pragma unroll
        for (int nt = 0; nt < 4; nt++)
#pragma unroll
            for (int q = 0; q < 4; q++) acc[mt][nt][q] = 0.f;

    const int S = K / 32;   // 8
#pragma unroll
    for (int p = 0; p < 3; p++){
        issue_stage_h(da + p*STAGE_B, db + p*STAGE_B, ap, bp, p);
        CP_COMMIT();
    }

    for (int i = 0; i < S; i++){
        CP_WAIT2();
        __syncthreads();
        const char* st = smc + (i & 3)*STAGE_B;
        compute_tile_h(st, st + SEC_B, wm, wn, lr, lc, acc);
        __syncthreads();
        if (i + 3 < S){
            int s = (i + 3) & 3;
            issue_stage_h(da + s*STAGE_B, db + s*STAGE_B, ap, bp, i + 3);
        }
        CP_COMMIT();
    }

#pragma unroll
    for (int mt = 0; mt < 4; mt++){
        int r0 = bm + wm + mt*16 + lr;
        int b0_ = r0 >> 6, n0 = r0 & 63;
        int b1_ = (r0+8) >> 6, n1 = (r0+8) & 63;
#pragma unroll
        for (int nt = 0; nt < 4; nt++){
            int c0 = bn + wn + nt*8 + lc*2;
            int s2 = c0 >> 8, rem = c0 & 255;
            int h = rem >> 5, d = rem & 31;
            float bv0, bv1;
            if (s2 == 0){ bv0 = qb[rem]; bv1 = qb[rem+1]; }
            else if (s2 == 2){ bv0 = vb[rem]; bv1 = vb[rem+1]; }
            else { bv0 = 0.f; bv1 = 0.f; }
            size_t hb = ((size_t)(s2*BWIN)*NHEADS + (size_t)h)*2048 + d;
            *(float2*)(g_qkv + hb + ((size_t)b0_*NHEADS)*2048 + n0*32) =
                make_float2(acc[mt][nt][0] + bv0, acc[mt][nt][1] + bv1);
            *(float2*)(g_qkv + hb + ((size_t)b1_*NHEADS)*2048 + n1*32) =
                make_float2(acc[mt][nt][2] + bv0, acc[mt][nt][3] + bv1);
        }
    }
}

// ---------------- attention: one (window, head) per block, chunked online softmax ----------------
__global__ __launch_bounds__(64) void k_attn(const float* __restrict__ ls){
    const int b_ = blockIdx.x;
    const int hh = blockIdx.y;
    const int n  = threadIdx.x;
    __shared__ float kn[64][32];
    __shared__ float vs[64][32];
    __shared__ int   rg[64];

    const size_t sstride = (size_t)BWIN * NHEADS * 64 * 32;
    const size_t base = ((size_t)b_*NHEADS + hh)*(64*32) + n*32;
    const float* qp = g_qkv + base;
    const float* kp = g_qkv + sstride + base;
    const float* vp = g_qkv + 2*sstride + base;

    float qr[32]; float sacc = 0.f;
#pragma unroll
    for (int d = 0; d < 32; d++){ qr[d] = qp[d]; sacc = fmaf(qr[d], qr[d], sacc); }
    float qi = rsqrtf(fmaxf(sacc, 1e-12f));
#pragma unroll
    for (int d = 0; d < 32; d++) qr[d] *= qi;

    sacc = 0.f; float kr[32];
#pragma unroll
    for (int d = 0; d < 32; d++){ kr[d] = kp[d]; sacc = fmaf(kr[d], kr[d], sacc); }
    float ki = rsqrtf(fmaxf(sacc, 1e-12f));
#pragma unroll
    for (int d = 0; d < 32; d++) kn[n][d] = kr[d]*ki;
#pragma unroll
    for (int d = 0; d < 32; d++) vs[n][d] = vp[d];

    int wid = b_ & 63;
    int gh = (wid >> 3)*8 + (n >> 3);
    int gw = (wid & 7)*8 + (n & 7);
    int hr = gh < 56 ? 0 : (gh < 60 ? 1 : 2);
    int wr = gw < 56 ? 0 : (gw < 60 ? 1 : 2);
    rg[n] = hr*3 + wr;
    __syncthreads();

    float scale = expf(fminf(ls[hh], 4.6051701859880914f));
    const float* rp = g_rpb + (hh*64 + n)*64;
    int myreg = hr*3 + wr;

    float mx = -1e30f, sum = 0.f;
    float acc[32];
#pragma unroll
    for (int d = 0; d < 32; d++) acc[d] = 0.f;

    for (int cb = 0; cb < 64; cb += 16){
        float lg[16]; float cmax = -1e30f;
#pragma unroll
        for (int j = 0; j < 16; j++){
            int m = cb + j;
            float dot = 0.f;
#pragma unroll
            for (int d = 0; d < 32; d++) dot = fmaf(qr[d], kn[m][d], dot);
            float v = fmaf(dot, scale, rp[m]);
            if (rg[m] != myreg) v -= 100.f;
            lg[j] = v;
            cmax = fmaxf(cmax, v);
        }
        float nm = fmaxf(mx, cmax);
        float corr = expf(mx - nm);
        sum *= corr;
#pragma unroll
        for (int d = 0; d < 32; d++) acc[d] *= corr;
#pragma unroll
        for (int j = 0; j < 16; j++){
            float p = expf(lg[j] - nm);
            sum += p;
            const float* vr = vs[cb + j];
#pragma unroll
            for (int d = 0; d < 32; d++) acc[d] = fmaf(p, vr[d], acc[d]);
        }
        mx = nm;
    }
    float inv = 1.f / sum;

    __half* op = g_attn_h + ((size_t)b_*64 + n)*CDIM + hh*32;
#pragma unroll
    for (int d = 0; d < 32; d += 2)
        *(__half2*)(op + d) = __floats2half2_rn(acc[d]*inv, acc[d+1]*inv);
}

// ---------------- LN1 + residual, scatter; fp32 residual + fp16 GEMM operand ----------------
__global__ void k_ln1(const float* __restrict__ x, const float* __restrict__ sc,
                      const float* __restrict__ bi){
    int r    = blockIdx.x*8 + (threadIdx.x >> 5);
    int lane = threadIdx.x & 31;
    const float* row = g_proj + (size_t)r*CDIM;
    float v[8]; float s = 0.f;
#pragma unroll
    for (int t = 0; t < 8; t++){ v[t] = row[lane + t*32]; s += v[t]; }
    s = warp_sum(s);
    float mu = s * (1.f/256.f);
    float var = 0.f;
#pragma unroll
    for (int t = 0; t < 8; t++){ float d = v[t]-mu; var = fmaf(d, d, var); }
    var = warp_sum(var) * (1.f/256.f);
    float invs = rsqrtf(var + 1e-6f);
    int dst = g_gather[r];
    const float* xr = x + (size_t)dst*CDIM;
    float*  o  = g_x1  + (size_t)dst*CDIM;
    __half* oh = g_x1h + (size_t)dst*CDIM;
#pragma unroll
    for (int t = 0; t < 8; t++){
        int c = lane + t*32;
        float val = xr[c] + (v[t]-mu)*invs*sc[c] + bi[c];
        o[c]  = val;
        oh[c] = __float2half_rn(val);
    }
}

// ---------------- LN2 + residual -> d_out ----------------
__global__ void k_ln2(const float* __restrict__ sc, const float* __restrict__ bi,
                      float* __restrict__ out){
    int r    = blockIdx.x*8 + (threadIdx.x >> 5);
    int lane = threadIdx.x & 31;
    const float* row = g_h2 + (size_t)r*CDIM;
    float v[8]; float s = 0.f;
#pragma unroll
    for (int t = 0; t < 8; t++){ v[t] = row[lane + t*32]; s += v[t]; }
    s = warp_sum(s);
    float mu = s * (1.f/256.f);
    float var = 0.f;
#pragma unroll
    for (int t = 0; t < 8; t++){ float d = v[t]-mu; var = fmaf(d, d, var); }
    var = warp_sum(var) * (1.f/256.f);
    float invs = rsqrtf(var + 1e-6f);
    const float* x1r = g_x1 + (size_t)r*CDIM;
    float* o = out + (size_t)r*CDIM;
#pragma unroll
    for (int t = 0; t < 8; t++){
        int c = lane + t*32;
        o[c] = x1r[c] + (v[t]-mu)*invs*sc[c] + bi[c];
    }
}

// ---------------- launch ----------------
extern "C" void kernel_launch(void* const* d_in, const int* in_sizes, int n_in,
                              void* d_out, int out_size){
    const float* x      = (const float*)d_in[0];
    const float* qkv_w  = (const float*)d_in[1];
    const float* q_bias = (const float*)d_in[2];
    const float* v_bias = (const float*)d_in[3];
    const float* lscale = (const float*)d_in[4];
    const float* cpb_w1 = (const float*)d_in[5];
    const float* cpb_b1 = (const float*)d_in[6];
    const float* cpb_w2 = (const float*)d_in[7];
    const float* proj_w = (const float*)d_in[8];
    const float* proj_b = (const float*)d_in[9];
    const float* n1s    = (const float*)d_in[10];
    const float* n1b    = (const float*)d_in[11];
    const float* n2s    = (const float*)d_in[12];
    const float* n2b    = (const float*)d_in[13];
    const float* fc1_w  = (const float*)d_in[14];
    const float* fc1_b  = (const float*)d_in[15];
    const float* fc2_w  = (const float*)d_in[16];
    const float* fc2_b  = (const float*)d_in[17];
    float* out = (float*)d_out;

    void *p_xh, *p_attn_h, *p_proj, *p_x1h, *p_hidh, *p_h2;
    void *p_wq, *p_wp, *p_w1, *p_w2;
    cudaGetSymbolAddress(&p_xh,     g_xh);
    cudaGetSymbolAddress(&p_attn_h, g_attn_h);
    cudaGetSymbolAddress(&p_proj,   g_proj);
    cudaGetSymbolAddress(&p_x1h,    g_x1h);
    cudaGetSymbolAddress(&p_hidh,   g_hidh);
    cudaGetSymbolAddress(&p_h2,     g_h2);
    cudaGetSymbolAddress(&p_wq,     g_wq);
    cudaGetSymbolAddress(&p_wp,     g_wp);
    cudaGetSymbolAddress(&p_w1,     g_w1);
    cudaGetSymbolAddress(&p_w2,     g_w2);

    cudaFuncSetAttribute(gemm_h<0,0>, cudaFuncAttributeMaxDynamicSharedMemorySize, SMEM_GEMM);
    cudaFuncSetAttribute(gemm_h<1,1>, cudaFuncAttributeMaxDynamicSharedMemorySize, SMEM_GEMM);
    cudaFuncSetAttribute(gemm_h_qkv,  cudaFuncAttributeMaxDynamicSharedMemorySize, SMEM_GEMM);

    // 0: gather + x->fp16
    k_setup<<<(ROWS*CDIM/4)/256, 256>>>(x);
    // 1: CPB MLP + rpb
    k_cpb_rpb<<<1, 256>>>(cpb_w1, cpb_b1, cpb_w2);
    // 2: all weight transposes (fp16)
    k_transpose_all<<<dim3(32, 32, 4), dim3(32, 8)>>>(qkv_w, proj_w, fc1_w, fc2_w);
    // 3: QKV (131072 x 256) @ (256 x 768)
    gemm_h_qkv<<<dim3(6, ROWS/128), 256, SMEM_GEMM>>>((const __half*)p_xh,
            (const __half*)p_wq, q_bias, v_bias);
    // 4: attention
    k_attn<<<dim3(BWIN, NHEADS), 64>>>(lscale);
    // 5: proj (131072 x 256) @ (256 x 256)   <- ncu -s 5 lands here
    gemm_h<0,0><<<dim3(2, ROWS/128), 256, SMEM_GEMM>>>((const __half*)p_attn_h,
            (const __half*)p_wp, proj_b, p_proj, 256, 256);
    // 6: LN1 + residual + scatter
    k_ln1<<<ROWS/8, 256>>>(x, n1s, n1b);
    // 7: FC1 + GELU -> fp16
    gemm_h<1,1><<<dim3(8, ROWS/128), 256, SMEM_GEMM>>>((const __half*)p_x1h,
            (const __half*)p_w1, fc1_b, p_hidh, 256, 1024);
    // 8: FC2
    gemm_h<0,0><<<dim3(2, ROWS/128), 256, SMEM_GEMM>>>((const __half*)p_hidh,
            (const __half*)p_w2, fc2_b, p_h2, 1024, 256);
    // 9: LN2 + residual -> out
    k_ln2<<<ROWS/8, 256>>>(n2s, n2b, out);
}